// round 15
// baseline (speedup 1.0000x reference)
#include <cuda_runtime.h>
#include <cuda_fp16.h>
#include <mma.h>

using namespace nvcuda;

#define N_NODES 50000
#define N_PAD   50048            // 391 * 128
#define N_EDGES 800000
#define DIM 256

#define SCAN_ELEMS 512
#define SCAN_BLOCKS ((N_NODES + SCAN_ELEMS - 1) / SCAN_ELEMS)   // 98

// ---- scratch (device globals: no allocation allowed in kernel_launch) ----
__device__ __half g_hb[(size_t)N_PAD * DIM];   // x @ W, fp16 (rows >= N_NODES never read)
__device__ __half g_wf[DIM * DIM];             // fp16 W
__device__ float g_dinv[N_NODES];
__device__ int   g_deg[N_NODES];
__device__ int   g_rowstart[N_NODES + 1];
__device__ int   g_cursor[N_NODES];
__device__ int   g_csr_src[N_EDGES];
__device__ int   g_blocksum[SCAN_BLOCKS];
__device__ int   g_blockoff[SCAN_BLOCKS];

// ------------------------------------------------------------------
// W -> fp16
// ------------------------------------------------------------------
__global__ __launch_bounds__(256) void k_convert_w(const float* __restrict__ W) {
    int idx = blockIdx.x * blockDim.x + threadIdx.x;        // 16384 float4s
    if (idx >= DIM * DIM / 4) return;
    float4 v = *(const float4*)(W + (size_t)idx * 4);
    __half2 p0 = __floats2half2_rn(v.x, v.y);
    __half2 p1 = __floats2half2_rn(v.z, v.w);
    __half2* p = (__half2*)(g_wf + (size_t)idx * 4);
    p[0] = p0; p[1] = p1;
}

// ------------------------------------------------------------------
// degree histogram + CSR build
// ------------------------------------------------------------------
__global__ void k_count(const int* __restrict__ ei) {
    int e = blockIdx.x * blockDim.x + threadIdx.x;
    if (e < N_EDGES) atomicAdd(&g_deg[ei[N_EDGES + e]], 1);
}

__global__ __launch_bounds__(256) void k_scan_partial() {
    __shared__ int red[256];
    int base = blockIdx.x * SCAN_ELEMS + threadIdx.x * 2;
    int s = 0;
    if (base < N_NODES)     s += g_deg[base];
    if (base + 1 < N_NODES) s += g_deg[base + 1];
    red[threadIdx.x] = s;
    __syncthreads();
    for (int off = 128; off > 0; off >>= 1) {
        if (threadIdx.x < off) red[threadIdx.x] += red[threadIdx.x + off];
        __syncthreads();
    }
    if (threadIdx.x == 0) g_blocksum[blockIdx.x] = red[0];
}

__global__ __launch_bounds__(128) void k_scan_blocks() {
    __shared__ int sh[128];
    int t = threadIdx.x;
    int v = (t < SCAN_BLOCKS) ? g_blocksum[t] : 0;
    sh[t] = v;
    __syncthreads();
    for (int off = 1; off < 128; off <<= 1) {
        int u = (t >= off) ? sh[t - off] : 0;
        __syncthreads();
        sh[t] += u;
        __syncthreads();
    }
    if (t < SCAN_BLOCKS) g_blockoff[t] = sh[t] - v;
    if (t == 127) g_rowstart[N_NODES] = sh[127];
}

__global__ __launch_bounds__(256) void k_scan_write() {
    __shared__ int warp_sums[8];
    int t = threadIdx.x;
    int lane = t & 31, warp = t >> 5;
    int base = blockIdx.x * SCAN_ELEMS + t * 2;

    int v0 = (base < N_NODES) ? g_deg[base] : 0;
    int v1 = (base + 1 < N_NODES) ? g_deg[base + 1] : 0;
    int s = v0 + v1;

    int inc = s;
#pragma unroll
    for (int off = 1; off < 32; off <<= 1) {
        int u = __shfl_up_sync(0xffffffffu, inc, off);
        if (lane >= off) inc += u;
    }
    if (lane == 31) warp_sums[warp] = inc;
    __syncthreads();
    if (warp == 0) {
        int ws = (lane < 8) ? warp_sums[lane] : 0;
#pragma unroll
        for (int off = 1; off < 8; off <<= 1) {
            int u = __shfl_up_sync(0xffffffffu, ws, off);
            if (lane >= off) ws += u;
        }
        if (lane < 8) warp_sums[lane] = ws;
    }
    __syncthreads();
    int ex = inc - s + (warp > 0 ? warp_sums[warp - 1] : 0) + g_blockoff[blockIdx.x];

    if (base < N_NODES) {
        g_rowstart[base] = ex;
        g_cursor[base]   = ex;
        g_dinv[base]     = rsqrtf((float)(v0 + 1));
    }
    if (base + 1 < N_NODES) {
        g_rowstart[base + 1] = ex + v0;
        g_cursor[base + 1]   = ex + v0;
        g_dinv[base + 1]     = rsqrtf((float)(v1 + 1));
    }
}

__global__ void k_fill(const int* __restrict__ ei) {
    int e = blockIdx.x * blockDim.x + threadIdx.x;
    if (e < N_EDGES) {
        int src = ei[e];
        int dst = ei[N_EDGES + e];
        int pos = atomicAdd(&g_cursor[dst], 1);
        g_csr_src[pos] = src;
    }
}

// ------------------------------------------------------------------
// tensor-core GEMM, pure fp16 inputs, fp32 accum, fp16 output:
//   g_hb = fp16( fp16(x) @ fp16(W) )
// CTA tile 128x128, 8 warps (4x2) of 32x64, K-step 64 (halved barriers)
// ------------------------------------------------------------------
__global__ __launch_bounds__(256) void k_gemm_tc(const float* __restrict__ x) {
    const int LDA = 72;    // 64 + 8 pad (half elems)
    const int LDB = 136;   // 128 + 8 pad
    __shared__ __half As[128 * LDA];       // 18.0 KB
    __shared__ __half Bs[64 * LDB];        // 17.4 KB
    __shared__ float stage_s[8 * 256];     //  8.0 KB per-warp 16x16 staging

    int bm = blockIdx.y * 128;
    int bn = blockIdx.x * 128;
    int tid = threadIdx.x;
    int wid = tid >> 5;
    int lane = tid & 31;
    int wm = wid & 3;          // 0..3 -> 32-row band
    int wn = wid >> 2;         // 0..1 -> 64-col band

    wmma::fragment<wmma::accumulator, 16, 16, 16, float> cf[2][4];
#pragma unroll
    for (int i = 0; i < 2; ++i)
#pragma unroll
        for (int j = 0; j < 4; ++j) wmma::fill_fragment(cf[i][j], 0.f);

#pragma unroll 1
    for (int kk = 0; kk < 4; ++kk) {
        int k0 = kk * 64;

        // A tile: 128 rows x 64 cols fp32 -> fp16; 2048 float4 chunks
#pragma unroll
        for (int c = tid; c < 2048; c += 256) {
            int row = c >> 4;          // 0..127
            int f   = (c & 15) * 4;    // col offset within 64
            int grow = bm + row;
            float4 v = make_float4(0.f, 0.f, 0.f, 0.f);
            if (grow < N_NODES)
                v = *(const float4*)(x + (size_t)grow * DIM + k0 + f);
            __half2* p = (__half2*)(&As[row * LDA + f]);
            p[0] = __floats2half2_rn(v.x, v.y);
            p[1] = __floats2half2_rn(v.z, v.w);
        }
        // B tile: 64 rows x 128 cols fp16 = 1024 int4 chunks
#pragma unroll
        for (int c = tid; c < 1024; c += 256) {
            int row = c >> 4;
            int wi = (c & 15) * 8;
            *(int4*)(&Bs[row * LDB + wi]) =
                *(const int4*)(g_wf + (size_t)(k0 + row) * DIM + bn + wi);
        }
        __syncthreads();

#pragma unroll
        for (int ks = 0; ks < 64; ks += 16) {
            wmma::fragment<wmma::matrix_a, 16, 16, 16, __half, wmma::row_major> af[2];
            wmma::fragment<wmma::matrix_b, 16, 16, 16, __half, wmma::row_major> bf[4];
#pragma unroll
            for (int i = 0; i < 2; ++i)
                wmma::load_matrix_sync(af[i], &As[(wm * 32 + i * 16) * LDA + ks], LDA);
#pragma unroll
            for (int j = 0; j < 4; ++j)
                wmma::load_matrix_sync(bf[j], &Bs[ks * LDB + wn * 64 + j * 16], LDB);
#pragma unroll
            for (int i = 0; i < 2; ++i)
#pragma unroll
                for (int j = 0; j < 4; ++j)
                    wmma::mma_sync(cf[i][j], af[i], bf[j], cf[i][j]);
        }
        __syncthreads();
    }

    // epilogue: fp32 tile -> fp16 g_hb, via per-warp smem staging
    float* stg = &stage_s[wid * 256];
    int r  = lane >> 1;            // 0..15
    int cs = (lane & 1) * 8;       // 0 or 8
#pragma unroll
    for (int i = 0; i < 2; ++i)
#pragma unroll
        for (int j = 0; j < 4; ++j) {
            wmma::store_matrix_sync(stg, cf[i][j], 16, wmma::mem_row_major);
            __syncwarp();
            int row = bm + wm * 32 + i * 16 + r;
            int col = bn + wn * 64 + j * 16 + cs;
            const float* sp = &stg[r * 16 + cs];
            __half2 p0 = __floats2half2_rn(sp[0], sp[1]);
            __half2 p1 = __floats2half2_rn(sp[2], sp[3]);
            __half2 p2 = __floats2half2_rn(sp[4], sp[5]);
            __half2 p3 = __floats2half2_rn(sp[6], sp[7]);
            uint4 o;
            o.x = *(unsigned*)&p0; o.y = *(unsigned*)&p1;
            o.z = *(unsigned*)&p2; o.w = *(unsigned*)&p3;
            *(uint4*)(&g_hb[(size_t)row * DIM + col]) = o;
            __syncwarp();
        }
}

// ------------------------------------------------------------------
// gather-side aggregation + epilogue, fp16 h rows, software-pipelined,
// fp32 accumulation (R13 core — proven best).
// out = relu( dinv[i]*sum_nbr(h[s]*dinv[s]) + dinv[i]^2*h[i] + b ) + x
// ------------------------------------------------------------------
__global__ __launch_bounds__(256) void k_agg(const float* __restrict__ x,
                                             const float* __restrict__ bias,
                                             float* __restrict__ out) {
    int node = blockIdx.x * 8 + threadIdx.y;
    if (node >= N_NODES) return;
    int lane = threadIdx.x;            // 0..31
    int c8 = lane * 8;

    float acc[8];
#pragma unroll
    for (int c = 0; c < 8; ++c) acc[c] = 0.f;

    int start = g_rowstart[node];
    int end   = g_rowstart[node + 1];
    int n4    = (end - start) & ~3;
    int kend4 = start + n4;

#define FMA_ROW(V, W)                                                                              \
    {                                                                                              \
        float2 f;                                                                                  \
        f = __half22float2(*(__half2*)&(V).x); acc[0] = fmaf(f.x, (W), acc[0]); acc[1] = fmaf(f.y, (W), acc[1]); \
        f = __half22float2(*(__half2*)&(V).y); acc[2] = fmaf(f.x, (W), acc[2]); acc[3] = fmaf(f.y, (W), acc[3]); \
        f = __half22float2(*(__half2*)&(V).z); acc[4] = fmaf(f.x, (W), acc[4]); acc[5] = fmaf(f.y, (W), acc[5]); \
        f = __half22float2(*(__half2*)&(V).w); acc[6] = fmaf(f.x, (W), acc[6]); acc[7] = fmaf(f.y, (W), acc[7]); \
    }

    if (n4 > 0) {
        int k = start;
        int   i0 = g_csr_src[k + 0], i1 = g_csr_src[k + 1];
        int   i2 = g_csr_src[k + 2], i3 = g_csr_src[k + 3];
        float w0 = g_dinv[i0], w1 = g_dinv[i1], w2 = g_dinv[i2], w3 = g_dinv[i3];
        k += 4;

        while (k < kend4) {
            int j0 = g_csr_src[k + 0], j1 = g_csr_src[k + 1];
            int j2 = g_csr_src[k + 2], j3 = g_csr_src[k + 3];
            uint4 v0 = *(const uint4*)(&g_hb[(size_t)i0 * DIM + c8]);
            uint4 v1 = *(const uint4*)(&g_hb[(size_t)i1 * DIM + c8]);
            uint4 v2 = *(const uint4*)(&g_hb[(size_t)i2 * DIM + c8]);
            uint4 v3 = *(const uint4*)(&g_hb[(size_t)i3 * DIM + c8]);
            float u0 = g_dinv[j0], u1 = g_dinv[j1], u2 = g_dinv[j2], u3 = g_dinv[j3];
            FMA_ROW(v0, w0); FMA_ROW(v1, w1); FMA_ROW(v2, w2); FMA_ROW(v3, w3);
            i0 = j0; i1 = j1; i2 = j2; i3 = j3;
            w0 = u0; w1 = u1; w2 = u2; w3 = u3;
            k += 4;
        }
        uint4 v0 = *(const uint4*)(&g_hb[(size_t)i0 * DIM + c8]);
        uint4 v1 = *(const uint4*)(&g_hb[(size_t)i1 * DIM + c8]);
        uint4 v2 = *(const uint4*)(&g_hb[(size_t)i2 * DIM + c8]);
        uint4 v3 = *(const uint4*)(&g_hb[(size_t)i3 * DIM + c8]);
        FMA_ROW(v0, w0); FMA_ROW(v1, w1); FMA_ROW(v2, w2); FMA_ROW(v3, w3);
    }
    for (int t = kend4; t < end; ++t) {
        int s = g_csr_src[t];
        float w = g_dinv[s];
        uint4 v = *(const uint4*)(&g_hb[(size_t)s * DIM + c8]);
        FMA_ROW(v, w);
    }
#undef FMA_ROW

    float di = g_dinv[node];
    float sw = di * di;                    // self-loop norm
    size_t base = (size_t)node * DIM + c8;

    uint4 vs = *(const uint4*)(&g_hb[base]);
    float hs[8];
    {
        float2 f;
        f = __half22float2(*(__half2*)&vs.x); hs[0] = f.x; hs[1] = f.y;
        f = __half22float2(*(__half2*)&vs.y); hs[2] = f.x; hs[3] = f.y;
        f = __half22float2(*(__half2*)&vs.z); hs[4] = f.x; hs[5] = f.y;
        f = __half22float2(*(__half2*)&vs.w); hs[6] = f.x; hs[7] = f.y;
    }

    float4 xv0 = *(const float4*)(&x[base]);
    float4 xv1 = *(const float4*)(&x[base + 4]);
    float4 bv0 = *(const float4*)(&bias[c8]);
    float4 bv1 = *(const float4*)(&bias[c8 + 4]);
    float xr[8] = {xv0.x, xv0.y, xv0.z, xv0.w, xv1.x, xv1.y, xv1.z, xv1.w};
    float br[8] = {bv0.x, bv0.y, bv0.z, bv0.w, bv1.x, bv1.y, bv1.z, bv1.w};

    float r[8];
#pragma unroll
    for (int c = 0; c < 8; ++c)
        r[c] = fmaxf(fmaf(di, acc[c], fmaf(sw, hs[c], br[c])), 0.f) + xr[c];
    *(float4*)(&out[base])     = make_float4(r[0], r[1], r[2], r[3]);
    *(float4*)(&out[base + 4]) = make_float4(r[4], r[5], r[6], r[7]);
}

// ------------------------------------------------------------------
extern "C" void kernel_launch(void* const* d_in, const int* in_sizes, int n_in,
                              void* d_out, int out_size) {
    const float* x  = (const float*)d_in[0];
    const int*   ei = (const int*)d_in[1];     // JAX default x64-disabled: int32
    const float* W  = (const float*)d_in[2];
    const float* b  = (const float*)d_in[3];
    float* out = (float*)d_out;

    // Fork a side stream so the CSR build runs concurrently with the GEMM.
    cudaStream_t s2;
    cudaEvent_t ev_fork, ev_join;
    cudaStreamCreateWithFlags(&s2, cudaStreamNonBlocking);
    cudaEventCreateWithFlags(&ev_fork, cudaEventDisableTiming);
    cudaEventCreateWithFlags(&ev_join, cudaEventDisableTiming);

    cudaEventRecord(ev_fork, 0);
    cudaStreamWaitEvent(s2, ev_fork, 0);

    // --- branch A (default stream): GEMM chain ---
    k_convert_w<<<(DIM * DIM / 4 + 255) / 256, 256>>>(W);
    k_gemm_tc<<<dim3(2, N_PAD / 128), 256>>>(x);

    // --- branch B (s2): CSR-by-dst build ---
    void* degp = nullptr;
    cudaGetSymbolAddress(&degp, g_deg);
    cudaMemsetAsync(degp, 0, N_NODES * sizeof(int), s2);
    k_count<<<(N_EDGES + 255) / 256, 256, 0, s2>>>(ei);
    k_scan_partial<<<SCAN_BLOCKS, 256, 0, s2>>>();
    k_scan_blocks<<<1, 128, 0, s2>>>();
    k_scan_write<<<SCAN_BLOCKS, 256, 0, s2>>>();
    k_fill<<<(N_EDGES + 255) / 256, 256, 0, s2>>>(ei);

    // --- join, then aggregate + epilogue ---
    cudaEventRecord(ev_join, s2);
    cudaStreamWaitEvent(0, ev_join, 0);

    dim3 ab(32, 8);
    k_agg<<<(N_NODES + 7) / 8, ab>>>(x, b, out);
}

// round 16
// speedup vs baseline: 1.1412x; 1.1412x over previous
#include <cuda_runtime.h>
#include <cuda_fp16.h>
#include <mma.h>

using namespace nvcuda;

#define N_NODES 50000
#define N_PAD   50048            // 391 * 128
#define N_EDGES 800000
#define DIM 256

#define SCAN_ELEMS 512
#define SCAN_BLOCKS ((N_NODES + SCAN_ELEMS - 1) / SCAN_ELEMS)   // 98

// ---- scratch (device globals: no allocation allowed in kernel_launch) ----
__device__ __half g_hb[(size_t)N_PAD * DIM];   // x @ W, fp16 (rows >= N_NODES never read)
__device__ __half g_wf[DIM * DIM];             // fp16 W
__device__ float g_dinv[N_NODES];
__device__ int   g_deg[N_NODES];
__device__ int   g_rowstart[N_NODES + 1];
__device__ int   g_cursor[N_NODES];
__device__ int   g_csr_src[N_EDGES];
__device__ int   g_blocksum[SCAN_BLOCKS];

// ------------------------------------------------------------------
// W -> fp16
// ------------------------------------------------------------------
__global__ __launch_bounds__(256) void k_convert_w(const float* __restrict__ W) {
    int idx = blockIdx.x * blockDim.x + threadIdx.x;        // 16384 float4s
    if (idx >= DIM * DIM / 4) return;
    float4 v = *(const float4*)(W + (size_t)idx * 4);
    __half2 p0 = __floats2half2_rn(v.x, v.y);
    __half2 p1 = __floats2half2_rn(v.z, v.w);
    __half2* p = (__half2*)(g_wf + (size_t)idx * 4);
    p[0] = p0; p[1] = p1;
}

// ------------------------------------------------------------------
// degree histogram + CSR build
// ------------------------------------------------------------------
// 2 edges per thread (int2 dst loads)
__global__ void k_count(const int* __restrict__ ei) {
    int e2 = blockIdx.x * blockDim.x + threadIdx.x;
    int e = e2 * 2;
    if (e + 1 < N_EDGES) {
        int2 d = *(const int2*)(ei + N_EDGES + e);
        atomicAdd(&g_deg[d.x], 1);
        atomicAdd(&g_deg[d.y], 1);
    } else if (e < N_EDGES) {
        atomicAdd(&g_deg[ei[N_EDGES + e]], 1);
    }
}

__global__ __launch_bounds__(256) void k_scan_partial() {
    __shared__ int red[256];
    int base = blockIdx.x * SCAN_ELEMS + threadIdx.x * 2;
    int s = 0;
    if (base < N_NODES)     s += g_deg[base];
    if (base + 1 < N_NODES) s += g_deg[base + 1];
    red[threadIdx.x] = s;
    __syncthreads();
    for (int off = 128; off > 0; off >>= 1) {
        if (threadIdx.x < off) red[threadIdx.x] += red[threadIdx.x + off];
        __syncthreads();
    }
    if (threadIdx.x == 0) g_blocksum[blockIdx.x] = red[0];
}

// fused: every block redundantly scans the 98 block sums (cheap), then does
// its local scan + writes rowstart/cursor/dinv. One launch less on branch B.
__global__ __launch_bounds__(256) void k_scan_write() {
    __shared__ int bsum[128];
    __shared__ int warp_sums[8];
    int t = threadIdx.x;
    int lane = t & 31, warp = t >> 5;

    // stage A: inclusive scan of block sums (128 lanes cover 98 blocks)
    if (t < 128) {
        int v = (t < SCAN_BLOCKS) ? g_blocksum[t] : 0;
        bsum[t] = v;
    }
    __syncthreads();
    if (t < 128) {
        int acc = bsum[t];
        for (int off = 1; off < 128; off <<= 1) {
            int u = (t >= off) ? bsum[t - off] : 0;
            __syncthreads();
            bsum[t] = acc = acc + u;
            __syncthreads();
        }
    } else {
        for (int off = 1; off < 128; off <<= 1) { __syncthreads(); __syncthreads(); }
    }
    __syncthreads();
    int blockoff = (blockIdx.x > 0) ? bsum[blockIdx.x - 1] : 0;   // exclusive
    if (blockIdx.x == 0 && t == 0) g_rowstart[N_NODES] = bsum[SCAN_BLOCKS - 1];

    // stage B: local scan + write
    int base = blockIdx.x * SCAN_ELEMS + t * 2;
    int v0 = (base < N_NODES) ? g_deg[base] : 0;
    int v1 = (base + 1 < N_NODES) ? g_deg[base + 1] : 0;
    int s = v0 + v1;

    int inc = s;
#pragma unroll
    for (int off = 1; off < 32; off <<= 1) {
        int u = __shfl_up_sync(0xffffffffu, inc, off);
        if (lane >= off) inc += u;
    }
    if (lane == 31) warp_sums[warp] = inc;
    __syncthreads();
    if (warp == 0) {
        int ws = (lane < 8) ? warp_sums[lane] : 0;
#pragma unroll
        for (int off = 1; off < 8; off <<= 1) {
            int u = __shfl_up_sync(0xffffffffu, ws, off);
            if (lane >= off) ws += u;
        }
        if (lane < 8) warp_sums[lane] = ws;
    }
    __syncthreads();
    int ex = inc - s + (warp > 0 ? warp_sums[warp - 1] : 0) + blockoff;

    if (base < N_NODES) {
        g_rowstart[base] = ex;
        g_cursor[base]   = ex;
        g_dinv[base]     = rsqrtf((float)(v0 + 1));
    }
    if (base + 1 < N_NODES) {
        g_rowstart[base + 1] = ex + v0;
        g_cursor[base + 1]   = ex + v0;
        g_dinv[base + 1]     = rsqrtf((float)(v1 + 1));
    }
}

// 2 edges per thread (int2 src/dst loads)
__global__ void k_fill(const int* __restrict__ ei) {
    int e2 = blockIdx.x * blockDim.x + threadIdx.x;
    int e = e2 * 2;
    if (e + 1 < N_EDGES) {
        int2 sv = *(const int2*)(ei + e);
        int2 dv = *(const int2*)(ei + N_EDGES + e);
        int p0 = atomicAdd(&g_cursor[dv.x], 1);
        g_csr_src[p0] = sv.x;
        int p1 = atomicAdd(&g_cursor[dv.y], 1);
        g_csr_src[p1] = sv.y;
    } else if (e < N_EDGES) {
        int src = ei[e];
        int dst = ei[N_EDGES + e];
        int pos = atomicAdd(&g_cursor[dst], 1);
        g_csr_src[pos] = src;
    }
}

// ------------------------------------------------------------------
// tensor-core GEMM, pure fp16 inputs, fp32 accum, fp16 output:
//   g_hb = fp16( fp16(x) @ fp16(W) )
// CTA tile 128x128, 8 warps (4x2) of 32x64, K-step 32   (R13 config)
// ------------------------------------------------------------------
__global__ __launch_bounds__(256) void k_gemm_tc(const float* __restrict__ x) {
    const int LDA = 40;    // 32 + 8 pad (half elems)
    const int LDB = 136;   // 128 + 8 pad
    __shared__ __half As[128 * LDA];
    __shared__ __half Bs[32 * LDB];
    __shared__ float stage_s[8 * 256];     // per-warp 16x16 fp32 staging

    int bm = blockIdx.y * 128;
    int bn = blockIdx.x * 128;
    int tid = threadIdx.x;
    int wid = tid >> 5;
    int lane = tid & 31;
    int wm = wid & 3;          // 0..3 -> 32-row band
    int wn = wid >> 2;         // 0..1 -> 64-col band

    wmma::fragment<wmma::accumulator, 16, 16, 16, float> cf[2][4];
#pragma unroll
    for (int i = 0; i < 2; ++i)
#pragma unroll
        for (int j = 0; j < 4; ++j) wmma::fill_fragment(cf[i][j], 0.f);

#pragma unroll 1
    for (int kk = 0; kk < 8; ++kk) {
        int k0 = kk * 32;

        // A tile: 128 rows x 32 cols fp32 -> fp16; 1024 float4 chunks
#pragma unroll
        for (int c = tid; c < 1024; c += 256) {
            int row = c >> 3;          // 0..127
            int f   = (c & 7) * 4;     // col offset within 32
            int grow = bm + row;
            float4 v = make_float4(0.f, 0.f, 0.f, 0.f);
            if (grow < N_NODES)
                v = *(const float4*)(x + (size_t)grow * DIM + k0 + f);
            __half2* p = (__half2*)(&As[row * LDA + f]);
            p[0] = __floats2half2_rn(v.x, v.y);
            p[1] = __floats2half2_rn(v.z, v.w);
        }
        // B tile: 32 rows x 128 cols fp16 = 512 int4 chunks
#pragma unroll
        for (int c = tid; c < 512; c += 256) {
            int row = c >> 4;
            int wi = (c & 15) * 8;
            *(int4*)(&Bs[row * LDB + wi]) =
                *(const int4*)(g_wf + (size_t)(k0 + row) * DIM + bn + wi);
        }
        __syncthreads();

#pragma unroll
        for (int ks = 0; ks < 32; ks += 16) {
            wmma::fragment<wmma::matrix_a, 16, 16, 16, __half, wmma::row_major> af[2];
            wmma::fragment<wmma::matrix_b, 16, 16, 16, __half, wmma::row_major> bf[4];
#pragma unroll
            for (int i = 0; i < 2; ++i)
                wmma::load_matrix_sync(af[i], &As[(wm * 32 + i * 16) * LDA + ks], LDA);
#pragma unroll
            for (int j = 0; j < 4; ++j)
                wmma::load_matrix_sync(bf[j], &Bs[ks * LDB + wn * 64 + j * 16], LDB);
#pragma unroll
            for (int i = 0; i < 2; ++i)
#pragma unroll
                for (int j = 0; j < 4; ++j)
                    wmma::mma_sync(cf[i][j], af[i], bf[j], cf[i][j]);
        }
        __syncthreads();
    }

    // epilogue: fp32 tile -> fp16 g_hb, via per-warp smem staging
    float* stg = &stage_s[wid * 256];
    int r  = lane >> 1;            // 0..15
    int cs = (lane & 1) * 8;       // 0 or 8
#pragma unroll
    for (int i = 0; i < 2; ++i)
#pragma unroll
        for (int j = 0; j < 4; ++j) {
            wmma::store_matrix_sync(stg, cf[i][j], 16, wmma::mem_row_major);
            __syncwarp();
            int row = bm + wm * 32 + i * 16 + r;
            int col = bn + wn * 64 + j * 16 + cs;
            const float* sp = &stg[r * 16 + cs];
            __half2 p0 = __floats2half2_rn(sp[0], sp[1]);
            __half2 p1 = __floats2half2_rn(sp[2], sp[3]);
            __half2 p2 = __floats2half2_rn(sp[4], sp[5]);
            __half2 p3 = __floats2half2_rn(sp[6], sp[7]);
            uint4 o;
            o.x = *(unsigned*)&p0; o.y = *(unsigned*)&p1;
            o.z = *(unsigned*)&p2; o.w = *(unsigned*)&p3;
            *(uint4*)(&g_hb[(size_t)row * DIM + col]) = o;
            __syncwarp();
        }
}

// ------------------------------------------------------------------
// gather-side aggregation + epilogue, fp16 h rows, software-pipelined,
// fp32 accumulation (R13 core — proven best).
// out = relu( dinv[i]*sum_nbr(h[s]*dinv[s]) + dinv[i]^2*h[i] + b ) + x
// ------------------------------------------------------------------
__global__ __launch_bounds__(256) void k_agg(const float* __restrict__ x,
                                             const float* __restrict__ bias,
                                             float* __restrict__ out) {
    int node = blockIdx.x * 8 + threadIdx.y;
    if (node >= N_NODES) return;
    int lane = threadIdx.x;            // 0..31
    int c8 = lane * 8;

    float acc[8];
#pragma unroll
    for (int c = 0; c < 8; ++c) acc[c] = 0.f;

    int start = g_rowstart[node];
    int end   = g_rowstart[node + 1];
    int n4    = (end - start) & ~3;
    int kend4 = start + n4;

#define FMA_ROW(V, W)                                                                              \
    {                                                                                              \
        float2 f;                                                                                  \
        f = __half22float2(*(__half2*)&(V).x); acc[0] = fmaf(f.x, (W), acc[0]); acc[1] = fmaf(f.y, (W), acc[1]); \
        f = __half22float2(*(__half2*)&(V).y); acc[2] = fmaf(f.x, (W), acc[2]); acc[3] = fmaf(f.y, (W), acc[3]); \
        f = __half22float2(*(__half2*)&(V).z); acc[4] = fmaf(f.x, (W), acc[4]); acc[5] = fmaf(f.y, (W), acc[5]); \
        f = __half22float2(*(__half2*)&(V).w); acc[6] = fmaf(f.x, (W), acc[6]); acc[7] = fmaf(f.y, (W), acc[7]); \
    }

    if (n4 > 0) {
        int k = start;
        int   i0 = g_csr_src[k + 0], i1 = g_csr_src[k + 1];
        int   i2 = g_csr_src[k + 2], i3 = g_csr_src[k + 3];
        float w0 = g_dinv[i0], w1 = g_dinv[i1], w2 = g_dinv[i2], w3 = g_dinv[i3];
        k += 4;

        while (k < kend4) {
            int j0 = g_csr_src[k + 0], j1 = g_csr_src[k + 1];
            int j2 = g_csr_src[k + 2], j3 = g_csr_src[k + 3];
            uint4 v0 = *(const uint4*)(&g_hb[(size_t)i0 * DIM + c8]);
            uint4 v1 = *(const uint4*)(&g_hb[(size_t)i1 * DIM + c8]);
            uint4 v2 = *(const uint4*)(&g_hb[(size_t)i2 * DIM + c8]);
            uint4 v3 = *(const uint4*)(&g_hb[(size_t)i3 * DIM + c8]);
            float u0 = g_dinv[j0], u1 = g_dinv[j1], u2 = g_dinv[j2], u3 = g_dinv[j3];
            FMA_ROW(v0, w0); FMA_ROW(v1, w1); FMA_ROW(v2, w2); FMA_ROW(v3, w3);
            i0 = j0; i1 = j1; i2 = j2; i3 = j3;
            w0 = u0; w1 = u1; w2 = u2; w3 = u3;
            k += 4;
        }
        uint4 v0 = *(const uint4*)(&g_hb[(size_t)i0 * DIM + c8]);
        uint4 v1 = *(const uint4*)(&g_hb[(size_t)i1 * DIM + c8]);
        uint4 v2 = *(const uint4*)(&g_hb[(size_t)i2 * DIM + c8]);
        uint4 v3 = *(const uint4*)(&g_hb[(size_t)i3 * DIM + c8]);
        FMA_ROW(v0, w0); FMA_ROW(v1, w1); FMA_ROW(v2, w2); FMA_ROW(v3, w3);
    }
    for (int t = kend4; t < end; ++t) {
        int s = g_csr_src[t];
        float w = g_dinv[s];
        uint4 v = *(const uint4*)(&g_hb[(size_t)s * DIM + c8]);
        FMA_ROW(v, w);
    }
#undef FMA_ROW

    float di = g_dinv[node];
    float sw = di * di;                    // self-loop norm
    size_t base = (size_t)node * DIM + c8;

    uint4 vs = *(const uint4*)(&g_hb[base]);
    float hs[8];
    {
        float2 f;
        f = __half22float2(*(__half2*)&vs.x); hs[0] = f.x; hs[1] = f.y;
        f = __half22float2(*(__half2*)&vs.y); hs[2] = f.x; hs[3] = f.y;
        f = __half22float2(*(__half2*)&vs.z); hs[4] = f.x; hs[5] = f.y;
        f = __half22float2(*(__half2*)&vs.w); hs[6] = f.x; hs[7] = f.y;
    }

    float4 xv0 = *(const float4*)(&x[base]);
    float4 xv1 = *(const float4*)(&x[base + 4]);
    float4 bv0 = *(const float4*)(&bias[c8]);
    float4 bv1 = *(const float4*)(&bias[c8 + 4]);
    float xr[8] = {xv0.x, xv0.y, xv0.z, xv0.w, xv1.x, xv1.y, xv1.z, xv1.w};
    float br[8] = {bv0.x, bv0.y, bv0.z, bv0.w, bv1.x, bv1.y, bv1.z, bv1.w};

    float r[8];
#pragma unroll
    for (int c = 0; c < 8; ++c)
        r[c] = fmaxf(fmaf(di, acc[c], fmaf(sw, hs[c], br[c])), 0.f) + xr[c];
    *(float4*)(&out[base])     = make_float4(r[0], r[1], r[2], r[3]);
    *(float4*)(&out[base + 4]) = make_float4(r[4], r[5], r[6], r[7]);
}

// ------------------------------------------------------------------
extern "C" void kernel_launch(void* const* d_in, const int* in_sizes, int n_in,
                              void* d_out, int out_size) {
    const float* x  = (const float*)d_in[0];
    const int*   ei = (const int*)d_in[1];     // JAX default x64-disabled: int32
    const float* W  = (const float*)d_in[2];
    const float* b  = (const float*)d_in[3];
    float* out = (float*)d_out;

    // Fork a side stream so the CSR build runs concurrently with the GEMM.
    cudaStream_t s2;
    cudaEvent_t ev_fork, ev_join;
    cudaStreamCreateWithFlags(&s2, cudaStreamNonBlocking);
    cudaEventCreateWithFlags(&ev_fork, cudaEventDisableTiming);
    cudaEventCreateWithFlags(&ev_join, cudaEventDisableTiming);

    cudaEventRecord(ev_fork, 0);
    cudaStreamWaitEvent(s2, ev_fork, 0);

    // --- branch A (default stream): GEMM chain ---
    k_convert_w<<<(DIM * DIM / 4 + 255) / 256, 256>>>(W);
    k_gemm_tc<<<dim3(2, N_PAD / 128), 256>>>(x);

    // --- branch B (s2): CSR-by-dst build ---
    void* degp = nullptr;
    cudaGetSymbolAddress(&degp, g_deg);
    cudaMemsetAsync(degp, 0, N_NODES * sizeof(int), s2);
    k_count<<<(N_EDGES / 2 + 255) / 256, 256, 0, s2>>>(ei);
    k_scan_partial<<<SCAN_BLOCKS, 256, 0, s2>>>();
    k_scan_write<<<SCAN_BLOCKS, 256, 0, s2>>>();
    k_fill<<<(N_EDGES / 2 + 255) / 256, 256, 0, s2>>>(ei);

    // --- join, then aggregate + epilogue ---
    cudaEventRecord(ev_join, s2);
    cudaStreamWaitEvent(0, ev_join, 0);

    dim3 ab(32, 8);
    k_agg<<<(N_NODES + 7) / 8, ab>>>(x, b, out);
}